// round 15
// baseline (speedup 1.0000x reference)
#include <cuda_runtime.h>
#include <cuda_fp16.h>
#include <cstdint>

// Problem shapes (fixed by the dataset).
#define BB 2
#define TT 2048
#define DD 1024
#define HH 16
#define DKK 64
#define MTOT (BB*TT)     // 4096 rows
#define NQKV 1152        // fused projection width: 1024 Q + 64 K + 64 V

// softmax scale folded with log2(e): 0.125 * 1.4426950408889634
// Pre-applied to Wq during weight conversion -> S arrives in base-2 domain.
#define SM_SCALE 0.18033688011112042f

// ---------------------------------------------------------------------------
// Device scratch (allocation-free per harness rules).  All fp16.
// ---------------------------------------------------------------------------
__device__ unsigned short g_QKVh[MTOT * NQKV];   // QKV fp16 (Q pre-scaled)
__device__ unsigned short g_xh[MTOT * DD];       // x fp16
__device__ unsigned short g_Bhi[NQKV * DD];      // [Wq*s;Wk;Wv]^T fp16
__device__ unsigned short g_Yhi[MTOT * DD];      // Y fp16
__device__ unsigned short g_Wohi[DD * DD];       // Wo^T fp16

// ---------------------------------------------------------------------------
// Generic-PTX tensor helpers (NO arch-'a' features: work on plain sm_103).
// ---------------------------------------------------------------------------
__device__ __forceinline__ uint32_t smem_u32(const void* p) {
    uint32_t a;
    asm("{ .reg .u64 t; cvta.to.shared.u64 t, %1; cvt.u32.u64 %0, t; }"
        : "=r"(a) : "l"(p));
    return a;
}

__device__ __forceinline__ void ldsm_x4(uint32_t& r0, uint32_t& r1,
                                        uint32_t& r2, uint32_t& r3, uint32_t a) {
    asm volatile("ldmatrix.sync.aligned.m8n8.x4.shared.b16 {%0,%1,%2,%3}, [%4];"
                 : "=r"(r0), "=r"(r1), "=r"(r2), "=r"(r3) : "r"(a));
}
__device__ __forceinline__ void ldsm_x4_t(uint32_t& r0, uint32_t& r1,
                                          uint32_t& r2, uint32_t& r3, uint32_t a) {
    asm volatile("ldmatrix.sync.aligned.m8n8.x4.trans.shared.b16 {%0,%1,%2,%3}, [%4];"
                 : "=r"(r0), "=r"(r1), "=r"(r2), "=r"(r3) : "r"(a));
}

// fp16 tensor-core MMA, fp32 accumulate.
__device__ __forceinline__ void mma_f16(float* d, const uint32_t* a,
                                        const uint32_t* b) {
    asm volatile(
        "mma.sync.aligned.m16n8k16.row.col.f32.f16.f16.f32 "
        "{%0,%1,%2,%3}, {%4,%5,%6,%7}, {%8,%9}, {%0,%1,%2,%3};"
        : "+f"(d[0]), "+f"(d[1]), "+f"(d[2]), "+f"(d[3])
        : "r"(a[0]), "r"(a[1]), "r"(a[2]), "r"(a[3]), "r"(b[0]), "r"(b[1]));
}

__device__ __forceinline__ void cp_async16(uint32_t saddr, const void* g) {
    asm volatile("cp.async.cg.shared.global [%0], [%1], 16;" :: "r"(saddr), "l"(g));
}
#define CP_COMMIT() asm volatile("cp.async.commit_group;" ::: "memory")
#define CP_WAIT(n)  asm volatile("cp.async.wait_group %0;" :: "n"(n) : "memory")

// Fast 2^x (single MUFU op).
__device__ __forceinline__ float ex2(float x) {
    float r;
    asm("ex2.approx.ftz.f32 %0, %1;" : "=f"(r) : "f"(x));
    return r;
}

// Round two fp32 to a packed fp16x2.
__device__ __forceinline__ uint32_t pack2h(float a, float b) {
    __half2 H = __floats2half2_rn(a, b);
    return *reinterpret_cast<uint32_t*>(&H);
}

// ---------------------------------------------------------------------------
// Conversion kernels.
// ---------------------------------------------------------------------------
// Elementwise fp32 -> fp16 round (vectorized 4-wide).
__global__ __launch_bounds__(256) void conv_round(
    const float4* __restrict__ a, uint2* __restrict__ oh, int n4)
{
    int i = blockIdx.x * blockDim.x + threadIdx.x;
    if (i >= n4) return;
    float4 v = a[i];
    oh[i] = make_uint2(pack2h(v.x, v.y), pack2h(v.z, v.w));
}

// Fused transpose+round for ALL weights. blockIdx.z selects the tensor:
//   0: Wq [1024,1024] *SM_SCALE -> Bh  @ n_off 0   (pre-scaled logits)
//   1: Wk [1024,  64]           -> Bh  @ n_off 1024
//   2: Wv [1024,  64]           -> Bh  @ n_off 1088
//   3: Wo [1024,1024]           -> Woh @ n_off 0
__global__ __launch_bounds__(256) void convW_all(
    const float* __restrict__ Wq, const float* __restrict__ Wk,
    const float* __restrict__ Wv, const float* __restrict__ Wo,
    __half* __restrict__ Bh, __half* __restrict__ Woh)
{
    const int z = blockIdx.z;
    const float* W;
    __half* oh;
    int N, n_off;
    float scl = 1.f;
    if      (z == 0) { W = Wq; oh = Bh;  N = 1024; n_off = 0;    scl = SM_SCALE; }
    else if (z == 1) { W = Wk; oh = Bh;  N = 64;   n_off = 1024; }
    else if (z == 2) { W = Wv; oh = Bh;  N = 64;   n_off = 1088; }
    else             { W = Wo; oh = Woh; N = 1024; n_off = 0;    }
    if ((int)blockIdx.x * 32 >= N) return;

    __shared__ float t[32][33];
    const int k0 = blockIdx.y * 32, n0 = blockIdx.x * 32;
    const int tx = threadIdx.x & 31, ty = threadIdx.x >> 5;  // 32 x 8
#pragma unroll
    for (int j = 0; j < 4; ++j)
        t[ty + 8*j][tx] = W[(size_t)(k0 + ty + 8*j) * N + n0 + tx];
    __syncthreads();
#pragma unroll
    for (int j = 0; j < 4; ++j) {
        float v = t[tx][ty + 8*j] * scl;   // = W[k0+tx][n0+ty+8j]
        oh[(size_t)(n_off + n0 + ty + 8*j) * 1024 + k0 + tx] = __float2half(v);
    }
}

// ---------------------------------------------------------------------------
// fp16 GEMM via mma.sync: C = Ah * Bh^T (fp32 accum).
// CTA tile 128x128, 8 warps (each 32x64), K-stage 64, cp.async double buffer,
// 2 CTAs/SM (smem 73728 x2 = 147KB). HALF_OUT: emit fp16; else fp32.
// ---------------------------------------------------------------------------
#define ROWB 144                // 64 fp16 = 128B data + 16B pad
#define ARR_B (128 * ROWB)      // 18432 B
#define STAGE_B (2 * ARR_B)     // 36864 B (Ah, Bh)
#define GEMM_SMEM_BYTES (2 * STAGE_B)   // 73728 B

template<bool HALF_OUT>
__global__ __launch_bounds__(256, 2) void gemm_h(
    const __half* __restrict__ Ah, const __half* __restrict__ Bh,
    float* __restrict__ C, __half* __restrict__ Ch, int Kd, int ldc)
{
    extern __shared__ __align__(16) char smd[];
    const uint32_t sbase = smem_u32(smd);
    const int tid  = threadIdx.x;
    const int lane = tid & 31;
    const int w    = tid >> 5;
    const int m0 = blockIdx.y * 128;
    const int n0 = blockIdx.x * 128;
    const int mw = (w >> 1) * 32;
    const int nw = (w & 1) * 64;

    float acc[2][8][4];
#pragma unroll
    for (int mt = 0; mt < 2; ++mt)
#pragma unroll
        for (int n8 = 0; n8 < 8; ++n8)
#pragma unroll
            for (int q = 0; q < 4; ++q) acc[mt][n8][q] = 0.f;

    const int NS = Kd >> 6;   // K-stages of 64

    // --- stage loader: 2048 x 16B chunks, 8 per thread ---
    auto load_stage = [&](int s) {
        const int kt = s << 6;
        const uint32_t sb = sbase + (s & 1) * STAGE_B;
#pragma unroll
        for (int v = 0; v < 8; ++v) {
            int idx = v * 256 + tid;
            int arr = idx >> 10;         // 0=A, 1=B
            int r   = (idx >> 3) & 127;
            int c   = idx & 7;
            const __half* base = arr ? Bh : Ah;
            int grow = (arr ? n0 : m0) + r;
            cp_async16(sb + arr * ARR_B + r * ROWB + c * 16,
                       base + (size_t)grow * Kd + kt + c * 8);
        }
    };

    load_stage(0);
    CP_COMMIT();

    for (int s = 0; s < NS; ++s) {
        if (s + 1 < NS) { load_stage(s + 1); CP_COMMIT(); CP_WAIT(1); }
        else            { CP_WAIT(0); }
        __syncthreads();

        const uint32_t sb = sbase + (s & 1) * STAGE_B;
        const uint32_t aHb = sb + (mw + (lane & 15)) * ROWB + (lane >> 4) * 16;
        const uint32_t bRow = nw + ((lane >> 4) << 3) + (lane & 7);
        const uint32_t bHb = sb + ARR_B + bRow * ROWB + ((lane >> 3) & 1) * 16;

#pragma unroll
        for (int kk = 0; kk < 4; ++kk) {
            const uint32_t ko = kk * 32;       // 16 halves = 32B per k16 step
            uint32_t ah[2][4];
            ldsm_x4(ah[0][0], ah[0][1], ah[0][2], ah[0][3], aHb + ko);
            ldsm_x4(ah[1][0], ah[1][1], ah[1][2], ah[1][3], aHb + 16 * ROWB + ko);

            uint32_t bh[8][2];
#pragma unroll
            for (int g = 0; g < 4; ++g)
                ldsm_x4(bh[2*g][0], bh[2*g][1], bh[2*g+1][0], bh[2*g+1][1],
                        bHb + g * 16 * ROWB + ko);
#pragma unroll
            for (int mt = 0; mt < 2; ++mt)
#pragma unroll
                for (int n8 = 0; n8 < 8; ++n8)
                    mma_f16(acc[mt][n8], ah[mt], bh[n8]);
        }
        __syncthreads();
    }

    // Epilogue
#pragma unroll
    for (int mt = 0; mt < 2; ++mt) {
        const int row = m0 + mw + mt * 16 + (lane >> 2);
        const int col = n0 + nw + (lane & 3) * 2;
        if (HALF_OUT) {
            __half* h0 = Ch + (size_t)row * ldc + col;
            __half* h1 = Ch + (size_t)(row + 8) * ldc + col;
#pragma unroll
            for (int n8 = 0; n8 < 8; ++n8) {
                *(uint32_t*)(h0 + n8 * 8) = pack2h(acc[mt][n8][0], acc[mt][n8][1]);
                *(uint32_t*)(h1 + n8 * 8) = pack2h(acc[mt][n8][2], acc[mt][n8][3]);
            }
        } else {
            float* c0 = C + (size_t)row * ldc + col;
            float* c1 = C + (size_t)(row + 8) * ldc + col;
#pragma unroll
            for (int n8 = 0; n8 < 8; ++n8) {
                *(float2*)(c0 + n8 * 8) = make_float2(acc[mt][n8][0], acc[mt][n8][1]);
                *(float2*)(c1 + n8 * 8) = make_float2(acc[mt][n8][2], acc[mt][n8][3]);
            }
        }
    }
}

// ---------------------------------------------------------------------------
// Tensor-core flash attention (causal, multi-query, all-fp16 operands,
// fp32 accum). S = Qh*Kh (pre-scaled, base-2 domain); O += Ph*Vh.
// 3-stage cp.async ring, one barrier per iteration. Conditional O-rescale
// (skipped when the running max is unchanged, exact). Per-lane partial l.
// ---------------------------------------------------------------------------
#define FT_ROWB 144
#define FT_ARR  (64 * FT_ROWB)      // 9216 B
#define FT_STG  (2 * FT_ARR)        // Kh, Vh = 18432 B
#define FT_SMEM (3 * FT_STG)        // 55296 B (3-stage ring)

__global__ __launch_bounds__(256) void flash_tc(
    const __half* __restrict__ QKVh, __half* __restrict__ Yh)
{
    extern __shared__ __align__(16) char smd[];
    const uint32_t sbase = smem_u32(smd);
    const int tid = threadIdx.x, lane = tid & 31, wid = tid >> 5;
    const int h = blockIdx.y, b = blockIdx.z;
    const int qb = (int)gridDim.x - 1 - (int)blockIdx.x;   // longest first
    const int i0 = qb * 128;
    const int g = lane >> 2, qd = lane & 3;

    uint32_t qh[4][4];
    {
        const int r0 = i0 + wid * 16 + g;
        const size_t b0 = (size_t)(b * TT + r0) * NQKV + h * 64;
        const size_t b1 = b0 + (size_t)8 * NQKV;
#pragma unroll
        for (int t = 0; t < 4; ++t) {
            const int c = t * 16 + qd * 2;
            qh[t][0] = *(const uint32_t*)(QKVh + b0 + c);
            qh[t][1] = *(const uint32_t*)(QKVh + b1 + c);
            qh[t][2] = *(const uint32_t*)(QKVh + b0 + c + 8);
            qh[t][3] = *(const uint32_t*)(QKVh + b1 + c + 8);
        }
    }

    float o[8][4];
#pragma unroll
    for (int n8 = 0; n8 < 8; ++n8)
#pragma unroll
        for (int c = 0; c < 4; ++c) o[n8][c] = 0.f;
    float m0 = -1e30f, m1 = -1e30f, l0 = 0.f, l1 = 0.f;   // l: per-lane partial

    // --- K/V stage loader: 1024 x 16B chunks, 4 per thread; ring of 3 ---
    auto load_kv = [&](int it) {
        const int j0 = it * 64;
        const uint32_t sb = sbase + (it % 3) * FT_STG;
#pragma unroll
        for (int v = 0; v < 4; ++v) {
            int idx = v * 256 + tid;
            int arr = idx >> 9, r = (idx >> 3) & 63, c = idx & 7;   // arr: 0=K,1=V
            int col = (arr == 0 ? 1024 : 1088) + c * 8;
            cp_async16(sb + arr * FT_ARR + r * FT_ROWB + c * 16,
                       QKVh + (size_t)(b * TT + j0 + r) * NQKV + col);
        }
    };

    const int nIter = 2 * qb + 2;     // always >= 2
    load_kv(0); CP_COMMIT();
    load_kv(1); CP_COMMIT();

    for (int it = 0; it < nIter; ++it) {
        if (it + 1 < nIter) { CP_WAIT(1); }   // buffer `it` landed
        else                { CP_WAIT(0); }
        __syncthreads();                       // visibility + buffer-reuse safety
        if (it + 2 < nIter) { load_kv(it + 2); CP_COMMIT(); }

        const uint32_t sb = sbase + (it % 3) * FT_STG;

        // ---- S = Qh Kh^T (already scaled to base-2 logits) ----
        float s[8][4];
#pragma unroll
        for (int n8 = 0; n8 < 8; ++n8)
#pragma unroll
            for (int c = 0; c < 4; ++c) s[n8][c] = 0.f;

        const uint32_t kA = sb + (((lane >> 4) << 3) + (lane & 7)) * FT_ROWB
                          + ((lane >> 3) & 1) * 16;
#pragma unroll
        for (int t = 0; t < 4; ++t) {
            uint32_t kh[8][2];
#pragma unroll
            for (int gg = 0; gg < 4; ++gg)
                ldsm_x4(kh[2*gg][0], kh[2*gg][1], kh[2*gg+1][0], kh[2*gg+1][1],
                        kA + gg * 16 * FT_ROWB + t * 32);
#pragma unroll
            for (int n8 = 0; n8 < 8; ++n8) mma_f16(s[n8], qh[t], kh[n8]);
        }

        // ---- causal mask (diagonal tiles only) ----
        const int j0 = it * 64;
        const int r0 = i0 + wid * 16 + g;
        if (j0 + 63 > i0 + wid * 16) {
#pragma unroll
            for (int n8 = 0; n8 < 8; ++n8) {
                const int j = j0 + n8 * 8 + qd * 2;
                if (j     > r0)     s[n8][0] = -1e30f;
                if (j + 1 > r0)     s[n8][1] = -1e30f;
                if (j     > r0 + 8) s[n8][2] = -1e30f;
                if (j + 1 > r0 + 8) s[n8][3] = -1e30f;
            }
        }

        // ---- online softmax (register-resident, base-2 exp) ----
        float mx0 = -1e30f, mx1 = -1e30f;
#pragma unroll
        for (int n8 = 0; n8 < 8; ++n8) {
            mx0 = fmaxf(mx0, fmaxf(s[n8][0], s[n8][1]));
            mx1 = fmaxf(mx1, fmaxf(s[n8][2], s[n8][3]));
        }
        mx0 = fmaxf(mx0, __shfl_xor_sync(0xffffffffu, mx0, 1));
        mx0 = fmaxf(mx0, __shfl_xor_sync(0xffffffffu, mx0, 2));
        mx1 = fmaxf(mx1, __shfl_xor_sync(0xffffffffu, mx1, 1));
        mx1 = fmaxf(mx1, __shfl_xor_sync(0xffffffffu, mx1, 2));
        const float mn0 = fmaxf(m0, mx0), mn1 = fmaxf(m1, mx1);
        const bool unchanged = (mn0 == m0) && (mn1 == m1);

        float sum0 = 0.f, sum1 = 0.f;
        uint32_t ph[4][4];
#pragma unroll
        for (int t = 0; t < 4; ++t) {
            float p00 = ex2(s[2*t][0] - mn0),   p01 = ex2(s[2*t][1] - mn0);
            float p02 = ex2(s[2*t][2] - mn1),   p03 = ex2(s[2*t][3] - mn1);
            float p10 = ex2(s[2*t+1][0] - mn0), p11 = ex2(s[2*t+1][1] - mn0);
            float p12 = ex2(s[2*t+1][2] - mn1), p13 = ex2(s[2*t+1][3] - mn1);
            sum0 += p00 + p01 + p10 + p11;
            sum1 += p02 + p03 + p12 + p13;
            ph[t][0] = pack2h(p00, p01);
            ph[t][1] = pack2h(p02, p03);
            ph[t][2] = pack2h(p10, p11);
            ph[t][3] = pack2h(p12, p13);
        }

        // Rescale only when some row's max advanced (exact: ex2(0)==1).
        if (__all_sync(0xffffffffu, unchanged)) {
            l0 += sum0;
            l1 += sum1;
        } else {
            const float sc0 = ex2(m0 - mn0), sc1 = ex2(m1 - mn1);
            m0 = mn0; m1 = mn1;
            l0 = l0 * sc0 + sum0;
            l1 = l1 * sc1 + sum1;
#pragma unroll
            for (int n8 = 0; n8 < 8; ++n8) {
                o[n8][0] *= sc0; o[n8][1] *= sc0;
                o[n8][2] *= sc1; o[n8][3] *= sc1;
            }
        }

        // ---- O += Ph Vh ----
        const uint32_t vA = sb + FT_ARR
                          + ((lane & 7) + ((lane >> 3) & 1) * 8) * FT_ROWB
                          + (lane >> 4) * 16;
#pragma unroll
        for (int t = 0; t < 4; ++t) {
            uint32_t vh[8][2];
#pragma unroll
            for (int dg = 0; dg < 4; ++dg)
                ldsm_x4_t(vh[2*dg][0], vh[2*dg][1], vh[2*dg+1][0], vh[2*dg+1][1],
                          vA + t * 16 * FT_ROWB + dg * 32);
#pragma unroll
            for (int n8 = 0; n8 < 8; ++n8) mma_f16(o[n8], ph[t], vh[n8]);
        }
        // no trailing barrier: next-iter barrier precedes any buffer overwrite
    }

    // ---- epilogue: reduce l across quad, normalize, write fp16 ----
    l0 += __shfl_xor_sync(0xffffffffu, l0, 1);
    l0 += __shfl_xor_sync(0xffffffffu, l0, 2);
    l1 += __shfl_xor_sync(0xffffffffu, l1, 1);
    l1 += __shfl_xor_sync(0xffffffffu, l1, 2);
    const float inv0 = 1.f / l0, inv1 = 1.f / l1;
    const int r0 = i0 + wid * 16 + g;
    const size_t off0 = (size_t)(b * TT + r0) * DD + h * 64 + qd * 2;
    const size_t off1 = off0 + (size_t)8 * DD;
#pragma unroll
    for (int n8 = 0; n8 < 8; ++n8) {
        *(uint32_t*)(Yh + off0 + n8 * 8) = pack2h(o[n8][0] * inv0, o[n8][1] * inv0);
        *(uint32_t*)(Yh + off1 + n8 * 8) = pack2h(o[n8][2] * inv1, o[n8][3] * inv1);
    }
}

// ---------------------------------------------------------------------------
extern "C" void kernel_launch(void* const* d_in, const int* in_sizes, int n_in,
                              void* d_out, int out_size)
{
    (void)in_sizes; (void)n_in; (void)out_size;
    const float* x  = (const float*)d_in[0];
    const float* Wq = (const float*)d_in[1];
    const float* Wk = (const float*)d_in[2];
    const float* Wv = (const float*)d_in[3];
    const float* Wo = (const float*)d_in[4];
    float* out = (float*)d_out;

    unsigned short *qkvh, *xh, *Bh, *Yh, *Woh;
    cudaGetSymbolAddress((void**)&qkvh, g_QKVh);
    cudaGetSymbolAddress((void**)&xh, g_xh);
    cudaGetSymbolAddress((void**)&Bh, g_Bhi);
    cudaGetSymbolAddress((void**)&Yh, g_Yhi);
    cudaGetSymbolAddress((void**)&Woh, g_Wohi);

    cudaFuncSetAttribute((const void*)gemm_h<true>,
                         cudaFuncAttributeMaxDynamicSharedMemorySize, GEMM_SMEM_BYTES);
    cudaFuncSetAttribute((const void*)gemm_h<false>,
                         cudaFuncAttributeMaxDynamicSharedMemorySize, GEMM_SMEM_BYTES);
    cudaFuncSetAttribute(flash_tc,
                         cudaFuncAttributeMaxDynamicSharedMemorySize, FT_SMEM);

    const int n4x = MTOT * DD / 4;

    // 1) Round x -> fp16
    conv_round<<<n4x / 256, 256>>>((const float4*)x, (uint2*)xh, n4x);

    // 2) All weight transpose+round in ONE launch (Wq pre-scaled)
    convW_all<<<dim3(32, 32, 4), 256>>>(Wq, Wk, Wv, Wo,
                                        (__half*)Bh, (__half*)Woh);

    // 3) Fused QKV projection (fp16 out)
    gemm_h<true><<<dim3(NQKV / 128, MTOT / 128), 256, GEMM_SMEM_BYTES>>>(
        (const __half*)xh, (const __half*)Bh,
        nullptr, (__half*)qkvh, DD, NQKV);

    // 4) Flash attention -> Yh (fp16)
    flash_tc<<<dim3(TT / 128, HH, BB), 256, FT_SMEM>>>(
        (const __half*)qkvh, (__half*)Yh);

    // 5) Output projection: out = Yh @ Wo (fp32 out)
    gemm_h<false><<<dim3(DD / 128, MTOT / 128), 256, GEMM_SMEM_BYTES>>>(
        (const __half*)Yh, (const __half*)Woh,
        out, nullptr, DD, DD);
}

// round 16
// speedup vs baseline: 1.5488x; 1.5488x over previous
#include <cuda_runtime.h>
#include <cuda_fp16.h>
#include <cstdint>

// Problem shapes (fixed by the dataset).
#define BB 2
#define TT 2048
#define DD 1024
#define HH 16
#define DKK 64
#define MTOT (BB*TT)     // 4096 rows
#define NQKV 1152        // fused projection width: 1024 Q + 64 K + 64 V

// softmax scale folded with log2(e): 0.125 * 1.4426950408889634
// Pre-applied to Wq during weight conversion -> S arrives in base-2 domain.
#define SM_SCALE 0.18033688011112042f

// ---------------------------------------------------------------------------
// Device scratch (allocation-free per harness rules).  All fp16.
// ---------------------------------------------------------------------------
__device__ unsigned short g_QKVh[MTOT * NQKV];   // QKV fp16 (Q pre-scaled)
__device__ unsigned short g_xh[MTOT * DD];       // x fp16
__device__ unsigned short g_Bhi[NQKV * DD];      // [Wq*s;Wk;Wv]^T fp16
__device__ unsigned short g_Yhi[MTOT * DD];      // Y fp16
__device__ unsigned short g_Wohi[DD * DD];       // Wo^T fp16

// ---------------------------------------------------------------------------
// Generic-PTX tensor helpers (NO arch-'a' features: work on plain sm_103).
// ---------------------------------------------------------------------------
__device__ __forceinline__ uint32_t smem_u32(const void* p) {
    uint32_t a;
    asm("{ .reg .u64 t; cvta.to.shared.u64 t, %1; cvt.u32.u64 %0, t; }"
        : "=r"(a) : "l"(p));
    return a;
}

__device__ __forceinline__ void ldsm_x4(uint32_t& r0, uint32_t& r1,
                                        uint32_t& r2, uint32_t& r3, uint32_t a) {
    asm volatile("ldmatrix.sync.aligned.m8n8.x4.shared.b16 {%0,%1,%2,%3}, [%4];"
                 : "=r"(r0), "=r"(r1), "=r"(r2), "=r"(r3) : "r"(a));
}
__device__ __forceinline__ void ldsm_x4_t(uint32_t& r0, uint32_t& r1,
                                          uint32_t& r2, uint32_t& r3, uint32_t a) {
    asm volatile("ldmatrix.sync.aligned.m8n8.x4.trans.shared.b16 {%0,%1,%2,%3}, [%4];"
                 : "=r"(r0), "=r"(r1), "=r"(r2), "=r"(r3) : "r"(a));
}

// fp16 tensor-core MMA, fp32 accumulate.
__device__ __forceinline__ void mma_f16(float* d, const uint32_t* a,
                                        const uint32_t* b) {
    asm volatile(
        "mma.sync.aligned.m16n8k16.row.col.f32.f16.f16.f32 "
        "{%0,%1,%2,%3}, {%4,%5,%6,%7}, {%8,%9}, {%0,%1,%2,%3};"
        : "+f"(d[0]), "+f"(d[1]), "+f"(d[2]), "+f"(d[3])
        : "r"(a[0]), "r"(a[1]), "r"(a[2]), "r"(a[3]), "r"(b[0]), "r"(b[1]));
}

__device__ __forceinline__ void cp_async16(uint32_t saddr, const void* g) {
    asm volatile("cp.async.cg.shared.global [%0], [%1], 16;" :: "r"(saddr), "l"(g));
}
#define CP_COMMIT() asm volatile("cp.async.commit_group;" ::: "memory")
#define CP_WAIT(n)  asm volatile("cp.async.wait_group %0;" :: "n"(n) : "memory")

// Fast 2^x (single MUFU op).
__device__ __forceinline__ float ex2(float x) {
    float r;
    asm("ex2.approx.ftz.f32 %0, %1;" : "=f"(r) : "f"(x));
    return r;
}

// Round two fp32 to a packed fp16x2.
__device__ __forceinline__ uint32_t pack2h(float a, float b) {
    __half2 H = __floats2half2_rn(a, b);
    return *reinterpret_cast<uint32_t*>(&H);
}

// ---------------------------------------------------------------------------
// Conversion kernels.
// ---------------------------------------------------------------------------
// Elementwise fp32 -> fp16 round (vectorized 4-wide).
__global__ __launch_bounds__(256) void conv_round(
    const float4* __restrict__ a, uint2* __restrict__ oh, int n4)
{
    int i = blockIdx.x * blockDim.x + threadIdx.x;
    if (i >= n4) return;
    float4 v = a[i];
    oh[i] = make_uint2(pack2h(v.x, v.y), pack2h(v.z, v.w));
}

// Fused transpose+round for ALL weights. blockIdx.z selects the tensor:
//   0: Wq [1024,1024] *SM_SCALE -> Bh  @ n_off 0   (pre-scaled logits)
//   1: Wk [1024,  64]           -> Bh  @ n_off 1024
//   2: Wv [1024,  64]           -> Bh  @ n_off 1088
//   3: Wo [1024,1024]           -> Woh @ n_off 0
__global__ __launch_bounds__(256) void convW_all(
    const float* __restrict__ Wq, const float* __restrict__ Wk,
    const float* __restrict__ Wv, const float* __restrict__ Wo,
    __half* __restrict__ Bh, __half* __restrict__ Woh)
{
    const int z = blockIdx.z;
    const float* W;
    __half* oh;
    int N, n_off;
    float scl = 1.f;
    if      (z == 0) { W = Wq; oh = Bh;  N = 1024; n_off = 0;    scl = SM_SCALE; }
    else if (z == 1) { W = Wk; oh = Bh;  N = 64;   n_off = 1024; }
    else if (z == 2) { W = Wv; oh = Bh;  N = 64;   n_off = 1088; }
    else             { W = Wo; oh = Woh; N = 1024; n_off = 0;    }
    if ((int)blockIdx.x * 32 >= N) return;

    __shared__ float t[32][33];
    const int k0 = blockIdx.y * 32, n0 = blockIdx.x * 32;
    const int tx = threadIdx.x & 31, ty = threadIdx.x >> 5;  // 32 x 8
#pragma unroll
    for (int j = 0; j < 4; ++j)
        t[ty + 8*j][tx] = W[(size_t)(k0 + ty + 8*j) * N + n0 + tx];
    __syncthreads();
#pragma unroll
    for (int j = 0; j < 4; ++j) {
        float v = t[tx][ty + 8*j] * scl;   // = W[k0+tx][n0+ty+8j]
        oh[(size_t)(n_off + n0 + ty + 8*j) * 1024 + k0 + tx] = __float2half(v);
    }
}

// ---------------------------------------------------------------------------
// fp16 GEMM via mma.sync: C = Ah * Bh^T (fp32 accum).
// CTA tile 128x128, 8 warps (each 32x64), K-stage 64, cp.async double buffer,
// 2 CTAs/SM (smem 73728 x2 = 147KB). HALF_OUT: emit fp16; else fp32.
// ---------------------------------------------------------------------------
#define ROWB 144                // 64 fp16 = 128B data + 16B pad
#define ARR_B (128 * ROWB)      // 18432 B
#define STAGE_B (2 * ARR_B)     // 36864 B (Ah, Bh)
#define GEMM_SMEM_BYTES (2 * STAGE_B)   // 73728 B

template<bool HALF_OUT>
__global__ __launch_bounds__(256, 2) void gemm_h(
    const __half* __restrict__ Ah, const __half* __restrict__ Bh,
    float* __restrict__ C, __half* __restrict__ Ch, int Kd, int ldc)
{
    extern __shared__ __align__(16) char smd[];
    const uint32_t sbase = smem_u32(smd);
    const int tid  = threadIdx.x;
    const int lane = tid & 31;
    const int w    = tid >> 5;
    const int m0 = blockIdx.y * 128;
    const int n0 = blockIdx.x * 128;
    const int mw = (w >> 1) * 32;
    const int nw = (w & 1) * 64;

    float acc[2][8][4];
#pragma unroll
    for (int mt = 0; mt < 2; ++mt)
#pragma unroll
        for (int n8 = 0; n8 < 8; ++n8)
#pragma unroll
            for (int q = 0; q < 4; ++q) acc[mt][n8][q] = 0.f;

    const int NS = Kd >> 6;   // K-stages of 64

    // --- stage loader: 2048 x 16B chunks, 8 per thread ---
    auto load_stage = [&](int s) {
        const int kt = s << 6;
        const uint32_t sb = sbase + (s & 1) * STAGE_B;
#pragma unroll
        for (int v = 0; v < 8; ++v) {
            int idx = v * 256 + tid;
            int arr = idx >> 10;         // 0=A, 1=B
            int r   = (idx >> 3) & 127;
            int c   = idx & 7;
            const __half* base = arr ? Bh : Ah;
            int grow = (arr ? n0 : m0) + r;
            cp_async16(sb + arr * ARR_B + r * ROWB + c * 16,
                       base + (size_t)grow * Kd + kt + c * 8);
        }
    };

    load_stage(0);
    CP_COMMIT();

    for (int s = 0; s < NS; ++s) {
        if (s + 1 < NS) { load_stage(s + 1); CP_COMMIT(); CP_WAIT(1); }
        else            { CP_WAIT(0); }
        __syncthreads();

        const uint32_t sb = sbase + (s & 1) * STAGE_B;
        const uint32_t aHb = sb + (mw + (lane & 15)) * ROWB + (lane >> 4) * 16;
        const uint32_t bRow = nw + ((lane >> 4) << 3) + (lane & 7);
        const uint32_t bHb = sb + ARR_B + bRow * ROWB + ((lane >> 3) & 1) * 16;

#pragma unroll
        for (int kk = 0; kk < 4; ++kk) {
            const uint32_t ko = kk * 32;       // 16 halves = 32B per k16 step
            uint32_t ah[2][4];
            ldsm_x4(ah[0][0], ah[0][1], ah[0][2], ah[0][3], aHb + ko);
            ldsm_x4(ah[1][0], ah[1][1], ah[1][2], ah[1][3], aHb + 16 * ROWB + ko);

            uint32_t bh[8][2];
#pragma unroll
            for (int g = 0; g < 4; ++g)
                ldsm_x4(bh[2*g][0], bh[2*g][1], bh[2*g+1][0], bh[2*g+1][1],
                        bHb + g * 16 * ROWB + ko);
#pragma unroll
            for (int mt = 0; mt < 2; ++mt)
#pragma unroll
                for (int n8 = 0; n8 < 8; ++n8)
                    mma_f16(acc[mt][n8], ah[mt], bh[n8]);
        }
        __syncthreads();
    }

    // Epilogue
#pragma unroll
    for (int mt = 0; mt < 2; ++mt) {
        const int row = m0 + mw + mt * 16 + (lane >> 2);
        const int col = n0 + nw + (lane & 3) * 2;
        if (HALF_OUT) {
            __half* h0 = Ch + (size_t)row * ldc + col;
            __half* h1 = Ch + (size_t)(row + 8) * ldc + col;
#pragma unroll
            for (int n8 = 0; n8 < 8; ++n8) {
                *(uint32_t*)(h0 + n8 * 8) = pack2h(acc[mt][n8][0], acc[mt][n8][1]);
                *(uint32_t*)(h1 + n8 * 8) = pack2h(acc[mt][n8][2], acc[mt][n8][3]);
            }
        } else {
            float* c0 = C + (size_t)row * ldc + col;
            float* c1 = C + (size_t)(row + 8) * ldc + col;
#pragma unroll
            for (int n8 = 0; n8 < 8; ++n8) {
                *(float2*)(c0 + n8 * 8) = make_float2(acc[mt][n8][0], acc[mt][n8][1]);
                *(float2*)(c1 + n8 * 8) = make_float2(acc[mt][n8][2], acc[mt][n8][3]);
            }
        }
    }
}

// ---------------------------------------------------------------------------
// Tensor-core flash attention (causal, multi-query, all-fp16 operands,
// fp32 accum). S = Qh*Kh (pre-scaled, base-2 domain); O += Ph*Vh.
// 3-stage cp.async ring, one barrier per iteration. Straight-line softmax
// (unconditional rescale — R15 showed branching here is a net loss).
// Per-lane partial l, quad-reduced once in the epilogue.
// ---------------------------------------------------------------------------
#define FT_ROWB 144
#define FT_ARR  (64 * FT_ROWB)      // 9216 B
#define FT_STG  (2 * FT_ARR)        // Kh, Vh = 18432 B
#define FT_SMEM (3 * FT_STG)        // 55296 B (3-stage ring)

__global__ __launch_bounds__(256) void flash_tc(
    const __half* __restrict__ QKVh, __half* __restrict__ Yh)
{
    extern __shared__ __align__(16) char smd[];
    const uint32_t sbase = smem_u32(smd);
    const int tid = threadIdx.x, lane = tid & 31, wid = tid >> 5;
    const int h = blockIdx.y, b = blockIdx.z;
    const int qb = (int)gridDim.x - 1 - (int)blockIdx.x;   // longest first
    const int i0 = qb * 128;
    const int g = lane >> 2, qd = lane & 3;

    uint32_t qh[4][4];
    {
        const int r0 = i0 + wid * 16 + g;
        const size_t b0 = (size_t)(b * TT + r0) * NQKV + h * 64;
        const size_t b1 = b0 + (size_t)8 * NQKV;
#pragma unroll
        for (int t = 0; t < 4; ++t) {
            const int c = t * 16 + qd * 2;
            qh[t][0] = *(const uint32_t*)(QKVh + b0 + c);
            qh[t][1] = *(const uint32_t*)(QKVh + b1 + c);
            qh[t][2] = *(const uint32_t*)(QKVh + b0 + c + 8);
            qh[t][3] = *(const uint32_t*)(QKVh + b1 + c + 8);
        }
    }

    float o[8][4];
#pragma unroll
    for (int n8 = 0; n8 < 8; ++n8)
#pragma unroll
        for (int c = 0; c < 4; ++c) o[n8][c] = 0.f;
    float m0 = -1e30f, m1 = -1e30f, l0 = 0.f, l1 = 0.f;   // l: per-lane partial

    // --- K/V stage loader: 1024 x 16B chunks, 4 per thread; ring of 3 ---
    auto load_kv = [&](int it) {
        const int j0 = it * 64;
        const uint32_t sb = sbase + (it % 3) * FT_STG;
#pragma unroll
        for (int v = 0; v < 4; ++v) {
            int idx = v * 256 + tid;
            int arr = idx >> 9, r = (idx >> 3) & 63, c = idx & 7;   // arr: 0=K,1=V
            int col = (arr == 0 ? 1024 : 1088) + c * 8;
            cp_async16(sb + arr * FT_ARR + r * FT_ROWB + c * 16,
                       QKVh + (size_t)(b * TT + j0 + r) * NQKV + col);
        }
    };

    const int nIter = 2 * qb + 2;     // always >= 2
    load_kv(0); CP_COMMIT();
    load_kv(1); CP_COMMIT();

    for (int it = 0; it < nIter; ++it) {
        if (it + 1 < nIter) { CP_WAIT(1); }   // buffer `it` landed
        else                { CP_WAIT(0); }
        __syncthreads();                       // visibility + buffer-reuse safety
        if (it + 2 < nIter) { load_kv(it + 2); CP_COMMIT(); }

        const uint32_t sb = sbase + (it % 3) * FT_STG;

        // ---- S = Qh Kh^T (already scaled to base-2 logits) ----
        float s[8][4];
#pragma unroll
        for (int n8 = 0; n8 < 8; ++n8)
#pragma unroll
            for (int c = 0; c < 4; ++c) s[n8][c] = 0.f;

        const uint32_t kA = sb + (((lane >> 4) << 3) + (lane & 7)) * FT_ROWB
                          + ((lane >> 3) & 1) * 16;
#pragma unroll
        for (int t = 0; t < 4; ++t) {
            uint32_t kh[8][2];
#pragma unroll
            for (int gg = 0; gg < 4; ++gg)
                ldsm_x4(kh[2*gg][0], kh[2*gg][1], kh[2*gg+1][0], kh[2*gg+1][1],
                        kA + gg * 16 * FT_ROWB + t * 32);
#pragma unroll
            for (int n8 = 0; n8 < 8; ++n8) mma_f16(s[n8], qh[t], kh[n8]);
        }

        // ---- causal mask (diagonal tiles only) ----
        const int j0 = it * 64;
        const int r0 = i0 + wid * 16 + g;
        if (j0 + 63 > i0 + wid * 16) {
#pragma unroll
            for (int n8 = 0; n8 < 8; ++n8) {
                const int j = j0 + n8 * 8 + qd * 2;
                if (j     > r0)     s[n8][0] = -1e30f;
                if (j + 1 > r0)     s[n8][1] = -1e30f;
                if (j     > r0 + 8) s[n8][2] = -1e30f;
                if (j + 1 > r0 + 8) s[n8][3] = -1e30f;
            }
        }

        // ---- online softmax (register-resident, base-2 exp, straight-line) ----
        float mx0 = -1e30f, mx1 = -1e30f;
#pragma unroll
        for (int n8 = 0; n8 < 8; ++n8) {
            mx0 = fmaxf(mx0, fmaxf(s[n8][0], s[n8][1]));
            mx1 = fmaxf(mx1, fmaxf(s[n8][2], s[n8][3]));
        }
        mx0 = fmaxf(mx0, __shfl_xor_sync(0xffffffffu, mx0, 1));
        mx0 = fmaxf(mx0, __shfl_xor_sync(0xffffffffu, mx0, 2));
        mx1 = fmaxf(mx1, __shfl_xor_sync(0xffffffffu, mx1, 1));
        mx1 = fmaxf(mx1, __shfl_xor_sync(0xffffffffu, mx1, 2));
        const float mn0 = fmaxf(m0, mx0), mn1 = fmaxf(m1, mx1);
        const float sc0 = ex2(m0 - mn0), sc1 = ex2(m1 - mn1);
        m0 = mn0; m1 = mn1;

        float sum0 = 0.f, sum1 = 0.f;
        uint32_t ph[4][4];
#pragma unroll
        for (int t = 0; t < 4; ++t) {
            float p00 = ex2(s[2*t][0] - mn0),   p01 = ex2(s[2*t][1] - mn0);
            float p02 = ex2(s[2*t][2] - mn1),   p03 = ex2(s[2*t][3] - mn1);
            float p10 = ex2(s[2*t+1][0] - mn0), p11 = ex2(s[2*t+1][1] - mn0);
            float p12 = ex2(s[2*t+1][2] - mn1), p13 = ex2(s[2*t+1][3] - mn1);
            sum0 += p00 + p01 + p10 + p11;
            sum1 += p02 + p03 + p12 + p13;
            ph[t][0] = pack2h(p00, p01);
            ph[t][1] = pack2h(p02, p03);
            ph[t][2] = pack2h(p10, p11);
            ph[t][3] = pack2h(p12, p13);
        }
        // per-lane partial l (sc uniform across quad; reduce once at the end)
        l0 = l0 * sc0 + sum0;
        l1 = l1 * sc1 + sum1;
#pragma unroll
        for (int n8 = 0; n8 < 8; ++n8) {
            o[n8][0] *= sc0; o[n8][1] *= sc0;
            o[n8][2] *= sc1; o[n8][3] *= sc1;
        }

        // ---- O += Ph Vh ----
        const uint32_t vA = sb + FT_ARR
                          + ((lane & 7) + ((lane >> 3) & 1) * 8) * FT_ROWB
                          + (lane >> 4) * 16;
#pragma unroll
        for (int t = 0; t < 4; ++t) {
            uint32_t vh[8][2];
#pragma unroll
            for (int dg = 0; dg < 4; ++dg)
                ldsm_x4_t(vh[2*dg][0], vh[2*dg][1], vh[2*dg+1][0], vh[2*dg+1][1],
                          vA + t * 16 * FT_ROWB + dg * 32);
#pragma unroll
            for (int n8 = 0; n8 < 8; ++n8) mma_f16(o[n8], ph[t], vh[n8]);
        }
        // no trailing barrier: next-iter barrier precedes any buffer overwrite
    }

    // ---- epilogue: reduce l across quad, normalize, write fp16 ----
    l0 += __shfl_xor_sync(0xffffffffu, l0, 1);
    l0 += __shfl_xor_sync(0xffffffffu, l0, 2);
    l1 += __shfl_xor_sync(0xffffffffu, l1, 1);
    l1 += __shfl_xor_sync(0xffffffffu, l1, 2);
    const float inv0 = 1.f / l0, inv1 = 1.f / l1;
    const int r0 = i0 + wid * 16 + g;
    const size_t off0 = (size_t)(b * TT + r0) * DD + h * 64 + qd * 2;
    const size_t off1 = off0 + (size_t)8 * DD;
#pragma unroll
    for (int n8 = 0; n8 < 8; ++n8) {
        *(uint32_t*)(Yh + off0 + n8 * 8) = pack2h(o[n8][0] * inv0, o[n8][1] * inv0);
        *(uint32_t*)(Yh + off1 + n8 * 8) = pack2h(o[n8][2] * inv1, o[n8][3] * inv1);
    }
}

// ---------------------------------------------------------------------------
extern "C" void kernel_launch(void* const* d_in, const int* in_sizes, int n_in,
                              void* d_out, int out_size)
{
    (void)in_sizes; (void)n_in; (void)out_size;
    const float* x  = (const float*)d_in[0];
    const float* Wq = (const float*)d_in[1];
    const float* Wk = (const float*)d_in[2];
    const float* Wv = (const float*)d_in[3];
    const float* Wo = (const float*)d_in[4];
    float* out = (float*)d_out;

    unsigned short *qkvh, *xh, *Bh, *Yh, *Woh;
    cudaGetSymbolAddress((void**)&qkvh, g_QKVh);
    cudaGetSymbolAddress((void**)&xh, g_xh);
    cudaGetSymbolAddress((void**)&Bh, g_Bhi);
    cudaGetSymbolAddress((void**)&Yh, g_Yhi);
    cudaGetSymbolAddress((void**)&Woh, g_Wohi);

    cudaFuncSetAttribute((const void*)gemm_h<true>,
                         cudaFuncAttributeMaxDynamicSharedMemorySize, GEMM_SMEM_BYTES);
    cudaFuncSetAttribute((const void*)gemm_h<false>,
                         cudaFuncAttributeMaxDynamicSharedMemorySize, GEMM_SMEM_BYTES);
    cudaFuncSetAttribute(flash_tc,
                         cudaFuncAttributeMaxDynamicSharedMemorySize, FT_SMEM);

    const int n4x = MTOT * DD / 4;

    // 1) Round x -> fp16
    conv_round<<<n4x / 256, 256>>>((const float4*)x, (uint2*)xh, n4x);

    // 2) All weight transpose+round in ONE launch (Wq pre-scaled)
    convW_all<<<dim3(32, 32, 4), 256>>>(Wq, Wk, Wv, Wo,
                                        (__half*)Bh, (__half*)Woh);

    // 3) Fused QKV projection (fp16 out)
    gemm_h<true><<<dim3(NQKV / 128, MTOT / 128), 256, GEMM_SMEM_BYTES>>>(
        (const __half*)xh, (const __half*)Bh,
        nullptr, (__half*)qkvh, DD, NQKV);

    // 4) Flash attention -> Yh (fp16)
    flash_tc<<<dim3(TT / 128, HH, BB), 256, FT_SMEM>>>(
        (const __half*)qkvh, (__half*)Yh);

    // 5) Output projection: out = Yh @ Wo (fp32 out)
    gemm_h<false><<<dim3(DD / 128, MTOT / 128), 256, GEMM_SMEM_BYTES>>>(
        (const __half*)Yh, (const __half*)Woh,
        out, nullptr, DD, DD);
}